// round 4
// baseline (speedup 1.0000x reference)
#include <cuda_runtime.h>
#include <cuda_bf16.h>
#include <cstdint>

// Problem constants (fixed by the dataset)
#define NN 50000
#define NE 800000
#define F_IN 128
#define F_HID 128
#define F_OUT 64

// Scratch (device globals: runtime allocation is forbidden).
// Reuse plan: g_bufA holds h1 (layer1), later h2 (layer2).
//             g_bufB holds agg1, finalized in place into act1.
__device__ float g_deg[NN];
__device__ float g_bufA[(size_t)NN * F_HID];
__device__ float g_bufB[(size_t)NN * F_HID];

// Host-side cached device addresses, resolved at program startup (static
// constructor) so the CUDA module (and its device globals) is loaded BEFORE
// the harness takes its memory baseline. No runtime API calls in
// kernel_launch besides kernel launches.
static float* s_deg  = nullptr;
static float* s_bufA = nullptr;
static float* s_bufB = nullptr;

namespace {
struct ModulePreload {
    ModulePreload() {
        void* p = nullptr;
        cudaGetSymbolAddress(&p, g_deg);  s_deg  = (float*)p;
        cudaGetSymbolAddress(&p, g_bufA); s_bufA = (float*)p;
        cudaGetSymbolAddress(&p, g_bufB); s_bufB = (float*)p;
    }
};
ModulePreload g_preload_instance;
}

// ---------------------------------------------------------------------------
__global__ void zero_deg_kernel() {
    int i = blockIdx.x * blockDim.x + threadIdx.x;
    if (i < NN) g_deg[i] = 0.0f;
}

__global__ void count_deg_kernel(const int* __restrict__ ei) {
    int e = blockIdx.x * blockDim.x + threadIdx.x;
    if (e < NE) {
        int dst = ei[NE + e];
        if ((unsigned)dst < NN) atomicAdd(&g_deg[dst], 1.0f);
    }
}

// ---------------------------------------------------------------------------
// C[M,N] = A[M,K=128] @ W[K,N]  (+bias)  (* max(deg[row],1) if SCALE)
// BM=64 rows/block, 256 threads, TM=8 x TN=(N/32) register tile.
template <int N, bool SCALE>
__global__ void __launch_bounds__(256)
gemm_kernel(const float* __restrict__ A, const float* __restrict__ W,
            const float* __restrict__ bias, float* __restrict__ C, int M) {
    constexpr int K = 128;
    constexpr int BM = 64, BK = 32;
    constexpr int TM = 8, TN = N / 32;

    __shared__ float As[BM][BK];   // 8 KB
    __shared__ float Ws[BK][N];    // 16 KB (N=128) / 8 KB (N=64)

    const int tid = threadIdx.x;
    const int tx = tid & 31;       // 0..31 -> column group
    const int ty = tid >> 5;       // 0..7  -> row group (one warp each)
    const int row0 = blockIdx.x * BM;

    float acc[TM][TN];
#pragma unroll
    for (int i = 0; i < TM; i++)
#pragma unroll
        for (int j = 0; j < TN; j++) acc[i][j] = 0.0f;

    for (int k0 = 0; k0 < K; k0 += BK) {
        // Load A tile: 64x32 floats = 512 float4, 2 per thread
#pragma unroll
        for (int i = 0; i < 2; i++) {
            int idx = tid + i * 256;        // float4 index
            int r = idx >> 3;               // 8 float4 per row
            int c4 = idx & 7;
            int grow = row0 + r;
            float4 v = make_float4(0.f, 0.f, 0.f, 0.f);
            if (grow < M)
                v = *(const float4*)&A[(size_t)grow * K + k0 + c4 * 4];
            *(float4*)&As[r][c4 * 4] = v;
        }
        // Load W tile: 32xN floats
        constexpr int WF4 = (BK * N / 4) / 256;   // 4 (N=128) or 2 (N=64)
#pragma unroll
        for (int i = 0; i < WF4; i++) {
            int idx = tid + i * 256;
            int r = idx / (N / 4);
            int c4 = idx % (N / 4);
            *(float4*)&Ws[r][c4 * 4] = *(const float4*)&W[(size_t)(k0 + r) * N + c4 * 4];
        }
        __syncthreads();

#pragma unroll
        for (int k = 0; k < BK; k++) {
            float a[TM];
#pragma unroll
            for (int i = 0; i < TM; i++) a[i] = As[ty * TM + i][k];
            float w[TN];
            if (TN == 4) {
                float4 wv = *(const float4*)&Ws[k][tx * 4];
                w[0] = wv.x; w[1] = wv.y; w[2] = wv.z; w[3] = wv.w;
            } else {
                float2 wv = *(const float2*)&Ws[k][tx * 2];
                w[0] = wv.x; w[1] = wv.y;
            }
#pragma unroll
            for (int i = 0; i < TM; i++)
#pragma unroll
                for (int j = 0; j < TN; j++) acc[i][j] += a[i] * w[j];
        }
        __syncthreads();
    }

#pragma unroll
    for (int i = 0; i < TM; i++) {
        int r = row0 + ty * TM + i;
        if (r < M) {
            float s = SCALE ? fmaxf(g_deg[r], 1.0f) : 1.0f;
#pragma unroll
            for (int j = 0; j < TN; j++) {
                float v = acc[i][j];
                int col = tx * TN + j;
                if (bias != nullptr) v += bias[col];
                C[(size_t)r * N + col] = v * s;
            }
        }
    }
}

// ---------------------------------------------------------------------------
// For each edge e: agg[dst[e]] += h[src[e]]   (F floats; each thread handles
// 4 consecutive floats, scattered via 4 scalar REDG.ADD.F32)
template <int F>
__global__ void __launch_bounds__(256)
scatter_kernel(const float* __restrict__ h, const int* __restrict__ ei,
               float* __restrict__ agg) {
    constexpr int C4 = F / 4;
    long long gid = (long long)blockIdx.x * blockDim.x + threadIdx.x;
    if (gid >= (long long)NE * C4) return;
    int e = (int)(gid / C4);
    int c = (int)(gid & (C4 - 1));
    int src = ei[e];
    int dst = ei[NE + e];
    if ((unsigned)src >= NN || (unsigned)dst >= NN) return;  // defensive
    float4 v = *(const float4*)(h + (size_t)src * F + c * 4);
    float* p = agg + (size_t)dst * F + c * 4;
    atomicAdd(p + 0, v.x);
    atomicAdd(p + 1, v.y);
    atomicAdd(p + 2, v.z);
    atomicAdd(p + 3, v.w);
}

// ---------------------------------------------------------------------------
// out = (relu?)(in / max(deg[row],1)), vectorized float4 (in-place safe)
template <int F, bool RELU>
__global__ void __launch_bounds__(256)
finalize_kernel(const float* __restrict__ in, float* __restrict__ out) {
    constexpr int C4 = F / 4;
    int i4 = blockIdx.x * blockDim.x + threadIdx.x;
    if (i4 >= NN * C4) return;
    int row = i4 / C4;
    float inv = 1.0f / fmaxf(g_deg[row], 1.0f);
    float4 v = *(const float4*)(in + (size_t)i4 * 4);
    v.x *= inv; v.y *= inv; v.z *= inv; v.w *= inv;
    if (RELU) {
        v.x = fmaxf(v.x, 0.f); v.y = fmaxf(v.y, 0.f);
        v.z = fmaxf(v.z, 0.f); v.w = fmaxf(v.w, 0.f);
    }
    *(float4*)(out + (size_t)i4 * 4) = v;
}

// ---------------------------------------------------------------------------
extern "C" void kernel_launch(void* const* d_in, const int* in_sizes, int n_in,
                              void* d_out, int out_size) {
    const float* x      = (const float*)d_in[0];
    const int*   ei     = (const int*)d_in[1];      // int32 (JAX x64 disabled)
    const float* W1     = (const float*)d_in[2];
    const float* lin1_w = (const float*)d_in[3];
    const float* lin1_b = (const float*)d_in[4];
    const float* W2     = (const float*)d_in[5];
    const float* lin2_w = (const float*)d_in[6];
    const float* lin2_b = (const float*)d_in[7];
    float*       out    = (float*)d_out;

    float* h1   = s_bufA;   // layer1: x@W1
    float* agg1 = s_bufB;   // layer1 accumulator -> act1 (in place)
    float* act1 = s_bufB;
    float* h2   = s_bufA;   // layer2: act1@W2 (reuses bufA)

    const int M = NN;
    const int gemm_blocks = (M + 63) / 64;

    // Degree (once; both layers share the graph)
    zero_deg_kernel<<<(NN + 255) / 256, 256>>>();
    count_deg_kernel<<<(NE + 255) / 256, 256>>>(ei);

    // ---- Layer 1 ----
    gemm_kernel<F_HID, false><<<gemm_blocks, 256>>>(x, W1, nullptr, h1, M);
    gemm_kernel<F_HID, true><<<gemm_blocks, 256>>>(x, lin1_w, lin1_b, agg1, M);
    {
        long long total = (long long)NE * (F_HID / 4);
        int blocks = (int)((total + 255) / 256);
        scatter_kernel<F_HID><<<blocks, 256>>>(h1, ei, agg1);
    }
    finalize_kernel<F_HID, true><<<(NN * (F_HID / 4) + 255) / 256, 256>>>(agg1, act1);

    // ---- Layer 2 ----
    gemm_kernel<F_OUT, false><<<gemm_blocks, 256>>>(act1, W2, nullptr, h2, M);
    gemm_kernel<F_OUT, true><<<gemm_blocks, 256>>>(act1, lin2_w, lin2_b, out, M);
    {
        long long total = (long long)NE * (F_OUT / 4);
        int blocks = (int)((total + 255) / 256);
        scatter_kernel<F_OUT><<<blocks, 256>>>(h2, ei, out);
    }
    finalize_kernel<F_OUT, false><<<(NN * (F_OUT / 4) + 255) / 256, 256>>>(out, out);
}

// round 5
// speedup vs baseline: 1.6386x; 1.6386x over previous
#include <cuda_runtime.h>
#include <cstdint>

// Problem constants (fixed by the dataset)
#define NN 50000
#define NE 800000
#define F_HID 128
#define F_OUT 64

// Scratch (device globals; runtime allocation forbidden)
__device__ int   g_cnt[NN];          // in-degree counts
__device__ int   g_rowptr[NN + 1];   // CSR row pointer (by dst)
__device__ int   g_cursor[NN];       // fill cursors
__device__ int   g_csrc[NE];         // CSR: src node per incoming edge
__device__ float g_h[(size_t)NN * F_HID];     // h1, later h2
__device__ float g_skip[(size_t)NN * F_HID];  // skip1, later skip2
__device__ float g_act1[(size_t)NN * F_HID];  // layer-1 activation

// Resolve device-global addresses at program startup so the module (and its
// globals) is loaded BEFORE the harness memory baseline. kernel_launch does
// nothing but kernel launches.
static float* s_h    = nullptr;
static float* s_skip = nullptr;
static float* s_act1 = nullptr;

namespace {
struct ModulePreload {
    ModulePreload() {
        void* p = nullptr;
        cudaGetSymbolAddress(&p, g_h);    s_h    = (float*)p;
        cudaGetSymbolAddress(&p, g_skip); s_skip = (float*)p;
        cudaGetSymbolAddress(&p, g_act1); s_act1 = (float*)p;
        cudaGetSymbolAddress(&p, g_cnt);  (void)p;
    }
};
ModulePreload g_preload_instance;
}

// ---------------------------------------------------------------------------
__global__ void zero_cnt_kernel() {
    int i = blockIdx.x * blockDim.x + threadIdx.x;
    if (i < NN) g_cnt[i] = 0;
}

__global__ void count_deg_kernel(const int* __restrict__ ei) {
    int e = blockIdx.x * blockDim.x + threadIdx.x;
    if (e < NE) {
        int dst = ei[NE + e];
        if ((unsigned)dst < NN) atomicAdd(&g_cnt[dst], 1);
    }
}

// Single-block exclusive scan of g_cnt -> g_rowptr / g_cursor.
__global__ void __launch_bounds__(1024) scan_kernel() {
    constexpr int T = 1024;
    constexpr int ITEMS = (NN + T - 1) / T;   // 49
    __shared__ int ssum[T];
    const int t = threadIdx.x;
    const int base = t * ITEMS;

    int s = 0;
#pragma unroll 4
    for (int i = 0; i < ITEMS; i++) {
        int idx = base + i;
        if (idx < NN) s += g_cnt[idx];
    }
    ssum[t] = s;
    __syncthreads();
    // Hillis-Steele inclusive scan over the 1024 per-thread sums
    for (int off = 1; off < T; off <<= 1) {
        int v = (t >= off) ? ssum[t - off] : 0;
        __syncthreads();
        ssum[t] += v;
        __syncthreads();
    }
    int run = ssum[t] - s;   // exclusive prefix for this thread's chunk
    for (int i = 0; i < ITEMS; i++) {
        int idx = base + i;
        if (idx < NN) {
            g_rowptr[idx] = run;
            g_cursor[idx] = run;
            run += g_cnt[idx];
        }
    }
    if (t == T - 1) g_rowptr[NN] = run;
}

__global__ void fill_csr_kernel(const int* __restrict__ ei) {
    int e = blockIdx.x * blockDim.x + threadIdx.x;
    if (e < NE) {
        int src = ei[e];
        int dst = ei[NE + e];
        if ((unsigned)src < NN && (unsigned)dst < NN) {
            int pos = atomicAdd(&g_cursor[dst], 1);
            g_csrc[pos] = src;
        }
    }
}

// ---------------------------------------------------------------------------
// C[M,N] = A[M,K=128] @ W[K,N] (+bias). BM=64 rows/block, 256 threads.
template <int N>
__global__ void __launch_bounds__(256)
gemm_kernel(const float* __restrict__ A, const float* __restrict__ W,
            const float* __restrict__ bias, float* __restrict__ C, int M) {
    constexpr int K = 128;
    constexpr int BM = 64, BK = 32;
    constexpr int TM = 8, TN = N / 32;

    __shared__ float As[BM][BK];
    __shared__ float Ws[BK][N];

    const int tid = threadIdx.x;
    const int tx = tid & 31;
    const int ty = tid >> 5;
    const int row0 = blockIdx.x * BM;

    float acc[TM][TN];
#pragma unroll
    for (int i = 0; i < TM; i++)
#pragma unroll
        for (int j = 0; j < TN; j++) acc[i][j] = 0.0f;

    for (int k0 = 0; k0 < K; k0 += BK) {
#pragma unroll
        for (int i = 0; i < 2; i++) {
            int idx = tid + i * 256;
            int r = idx >> 3;
            int c4 = idx & 7;
            int grow = row0 + r;
            float4 v = make_float4(0.f, 0.f, 0.f, 0.f);
            if (grow < M)
                v = *(const float4*)&A[(size_t)grow * K + k0 + c4 * 4];
            *(float4*)&As[r][c4 * 4] = v;
        }
        constexpr int WF4 = (BK * N / 4) / 256;
#pragma unroll
        for (int i = 0; i < WF4; i++) {
            int idx = tid + i * 256;
            int r = idx / (N / 4);
            int c4 = idx % (N / 4);
            *(float4*)&Ws[r][c4 * 4] = *(const float4*)&W[(size_t)(k0 + r) * N + c4 * 4];
        }
        __syncthreads();

#pragma unroll
        for (int k = 0; k < BK; k++) {
            float a[TM];
#pragma unroll
            for (int i = 0; i < TM; i++) a[i] = As[ty * TM + i][k];
            float w[TN];
            if (TN == 4) {
                float4 wv = *(const float4*)&Ws[k][tx * 4];
                w[0] = wv.x; w[1] = wv.y; w[2] = wv.z; w[3] = wv.w;
            } else {
                float2 wv = *(const float2*)&Ws[k][tx * 2];
                w[0] = wv.x; w[1] = wv.y;
            }
#pragma unroll
            for (int i = 0; i < TM; i++)
#pragma unroll
                for (int j = 0; j < TN; j++) acc[i][j] += a[i] * w[j];
        }
        __syncthreads();
    }

#pragma unroll
    for (int i = 0; i < TM; i++) {
        int r = row0 + ty * TM + i;
        if (r < M) {
#pragma unroll
            for (int j = 0; j < TN; j++) {
                float v = acc[i][j];
                int col = tx * TN + j;
                if (bias != nullptr) v += bias[col];
                C[(size_t)r * N + col] = v;
            }
        }
    }
}

// ---------------------------------------------------------------------------
// One warp per node: out[n] = (relu?)( mean_{src in N(n)} h[src] + skip[n] )
// F=128 -> float4/lane, F=64 -> float2/lane. Atomic-free gather.
template <int F, bool RELU>
__global__ void __launch_bounds__(256)
aggregate_kernel(const float* __restrict__ h, const float* __restrict__ skip,
                 float* __restrict__ out) {
    constexpr int VEC = F / 32;            // 4 or 2
    int warp = (blockIdx.x * 256 + threadIdx.x) >> 5;
    int lane = threadIdx.x & 31;
    if (warp >= NN) return;

    int beg = g_rowptr[warp];
    int end = g_rowptr[warp + 1];

    float acc[VEC];
#pragma unroll
    for (int v = 0; v < VEC; v++) acc[v] = 0.0f;

    for (int i = beg; i < end; i++) {
        int src = g_csrc[i];
        const float* hp = h + (size_t)src * F + lane * VEC;
        if (VEC == 4) {
            float4 hv = *(const float4*)hp;
            acc[0] += hv.x; acc[1] += hv.y; acc[2] += hv.z; acc[3] += hv.w;
        } else {
            float2 hv = *(const float2*)hp;
            acc[0] += hv.x; acc[1] += hv.y;
        }
    }

    float inv = 1.0f / fmaxf((float)(end - beg), 1.0f);
    const float* sp = skip + (size_t)warp * F + lane * VEC;
    float* op = out + (size_t)warp * F + lane * VEC;
    if (VEC == 4) {
        float4 sk = *(const float4*)sp;
        float4 r;
        r.x = acc[0] * inv + sk.x; r.y = acc[1] * inv + sk.y;
        r.z = acc[2] * inv + sk.z; r.w = acc[3] * inv + sk.w;
        if (RELU) {
            r.x = fmaxf(r.x, 0.f); r.y = fmaxf(r.y, 0.f);
            r.z = fmaxf(r.z, 0.f); r.w = fmaxf(r.w, 0.f);
        }
        *(float4*)op = r;
    } else {
        float2 sk = *(const float2*)sp;
        float2 r;
        r.x = acc[0] * inv + sk.x; r.y = acc[1] * inv + sk.y;
        if (RELU) { r.x = fmaxf(r.x, 0.f); r.y = fmaxf(r.y, 0.f); }
        *(float2*)op = r;
    }
}

// ---------------------------------------------------------------------------
extern "C" void kernel_launch(void* const* d_in, const int* in_sizes, int n_in,
                              void* d_out, int out_size) {
    const float* x      = (const float*)d_in[0];
    const int*   ei     = (const int*)d_in[1];      // int32
    const float* W1     = (const float*)d_in[2];
    const float* lin1_w = (const float*)d_in[3];
    const float* lin1_b = (const float*)d_in[4];
    const float* W2     = (const float*)d_in[5];
    const float* lin2_w = (const float*)d_in[6];
    const float* lin2_b = (const float*)d_in[7];
    float*       out    = (float*)d_out;

    const int M = NN;
    const int gemm_blocks = (M + 63) / 64;
    const int agg_blocks = (NN * 32 + 255) / 256;   // one warp per node

    // ---- CSR build (graph identical for both layers) ----
    zero_cnt_kernel<<<(NN + 255) / 256, 256>>>();
    count_deg_kernel<<<(NE + 255) / 256, 256>>>(ei);
    scan_kernel<<<1, 1024>>>();
    fill_csr_kernel<<<(NE + 255) / 256, 256>>>(ei);

    // ---- Layer 1 ----
    gemm_kernel<F_HID><<<gemm_blocks, 256>>>(x, W1, nullptr, s_h, M);
    gemm_kernel<F_HID><<<gemm_blocks, 256>>>(x, lin1_w, lin1_b, s_skip, M);
    aggregate_kernel<F_HID, true><<<agg_blocks, 256>>>(s_h, s_skip, s_act1);

    // ---- Layer 2 ----
    gemm_kernel<F_OUT><<<gemm_blocks, 256>>>(s_act1, W2, nullptr, s_h, M);
    gemm_kernel<F_OUT><<<gemm_blocks, 256>>>(s_act1, lin2_w, lin2_b, s_skip, M);
    aggregate_kernel<F_OUT, false><<<agg_blocks, 256>>>(s_h, s_skip, out);
}